// round 2
// baseline (speedup 1.0000x reference)
#include <cuda_runtime.h>

#define NROWS 32768
#define DOBS 256
#define HDIM 512
#define NA 32
#define NROLES 6

// ---------------- scratch (device globals; no allocation allowed) ----------
__device__ float g_obsn[NROWS * DOBS];   // LN(obs)
__device__ float g_e0[NROWS * HDIM];     // after layer0
__device__ float g_e1[NROWS * HDIM];     // after layer1 (+ route residual)
__device__ float g_r0[NROWS * 128];      // route hidden
__device__ int   g_rows[NROLES * NROWS]; // per-role row lists
__device__ int   g_cnt[NROLES];

// ---------------- small kernels -------------------------------------------
__global__ void k_copy4(const float4* __restrict__ src, float4* __restrict__ dst, int n4) {
    int i = blockIdx.x * blockDim.x + threadIdx.x;
    if (i < n4) dst[i] = src[i];
}

__global__ void k_zero_cnt() {
    if (threadIdx.x < NROLES) g_cnt[threadIdx.x] = 0;
}

__global__ void k_bucket(const int* __restrict__ role_ids) {
    int i = blockIdx.x * blockDim.x + threadIdx.x;
    if (i < NROWS) {
        int r = role_ids[i];
        int p = atomicAdd(&g_cnt[r], 1);
        g_rows[r * NROWS + p] = i;
    }
}

// LayerNorm over obs (256 dims), warp per row
__global__ void k_ln_obs(const float* __restrict__ obs, const float* __restrict__ sc,
                         const float* __restrict__ bi) {
    int warp = threadIdx.x >> 5, lane = threadIdx.x & 31;
    int row = blockIdx.x * 8 + warp;
    const float* src = obs + (size_t)row * DOBS;
    float x[8]; float s = 0.f, q = 0.f;
#pragma unroll
    for (int j = 0; j < 8; j++) { x[j] = src[lane + 32 * j]; s += x[j]; q += x[j] * x[j]; }
#pragma unroll
    for (int o = 16; o > 0; o >>= 1) {
        s += __shfl_xor_sync(0xffffffffu, s, o);
        q += __shfl_xor_sync(0xffffffffu, q, o);
    }
    float m = s * (1.f / DOBS);
    float v = q * (1.f / DOBS) - m * m;
    float rs = rsqrtf(v + 1e-5f);
    float* dst = g_obsn + (size_t)row * DOBS;
#pragma unroll
    for (int j = 0; j < 8; j++) {
        int d = lane + 32 * j;
        dst[d] = (x[j] - m) * rs * sc[d] + bi[d];
    }
}

// ---------------- fused GEMM + bias + relu + LayerNorm --------------------
// C(32768 x 512) = LN(relu(A(32768 x K) @ W(K x 512) + bias))
// tile: 32 rows x 512 cols per block (full rows -> in-block LN), 256 threads,
// each thread 8x8 outputs (rows ry*8+i, cols cx+64j).
__global__ __launch_bounds__(256) void k_gemm_ln(
    const float* __restrict__ A, const float* __restrict__ W,
    const float* __restrict__ bias, const float* __restrict__ lns,
    const float* __restrict__ lnb, float* __restrict__ out, int K)
{
    __shared__ __align__(16) float As[16][40];
    __shared__ __align__(16) float Bs[16][512];
    __shared__ float mrow[32], rrow[32];
    const int t = threadIdx.x;
    const int cx = t & 63;
    const int ry = t >> 6;
    const int row0 = blockIdx.x * 32;
    float acc[8][8];
#pragma unroll
    for (int i = 0; i < 8; i++)
#pragma unroll
        for (int j = 0; j < 8; j++) acc[i][j] = 0.f;

    const int ar = t >> 3;         // 0..31
    const int ak = (t & 7) << 1;   // 0,2,..,14
    for (int k0 = 0; k0 < K; k0 += 16) {
        float2 av2 = *reinterpret_cast<const float2*>(A + (size_t)(row0 + ar) * K + k0 + ak);
        As[ak][ar] = av2.x; As[ak + 1][ar] = av2.y;
#pragma unroll
        for (int i = 0; i < 8; i++) {
            int idx = t + i * 256;
            int kk = idx >> 7;
            int nn = (idx & 127) << 2;
            float4 v = *reinterpret_cast<const float4*>(W + (size_t)(k0 + kk) * HDIM + nn);
            *reinterpret_cast<float4*>(&Bs[kk][nn]) = v;
        }
        __syncthreads();
#pragma unroll
        for (int kk = 0; kk < 16; kk++) {
            float4 a0 = *reinterpret_cast<const float4*>(&As[kk][ry * 8]);
            float4 a1 = *reinterpret_cast<const float4*>(&As[kk][ry * 8 + 4]);
            float a[8] = {a0.x, a0.y, a0.z, a0.w, a1.x, a1.y, a1.z, a1.w};
            float b[8];
#pragma unroll
            for (int j = 0; j < 8; j++) b[j] = Bs[kk][cx + 64 * j];
#pragma unroll
            for (int i = 0; i < 8; i++)
#pragma unroll
                for (int j = 0; j < 8; j++) acc[i][j] = fmaf(a[i], b[j], acc[i][j]);
        }
        __syncthreads();
    }
    // bias + relu + per-row partial sums (reuse Bs as reduction scratch)
    float* redS = &Bs[0][0];
    float* redQ = redS + 2048;
    float bsv[8];
#pragma unroll
    for (int j = 0; j < 8; j++) bsv[j] = bias[cx + 64 * j];
#pragma unroll
    for (int i = 0; i < 8; i++) {
        float s = 0.f, q = 0.f;
#pragma unroll
        for (int j = 0; j < 8; j++) {
            float v = fmaxf(acc[i][j] + bsv[j], 0.f);
            acc[i][j] = v; s += v; q += v * v;
        }
        redS[(ry * 8 + i) * 64 + cx] = s;
        redQ[(ry * 8 + i) * 64 + cx] = q;
    }
    __syncthreads();
    if (t < 32) {   // deterministic serial reduce per row
        float ss = 0.f, qq = 0.f;
        for (int j = 0; j < 64; j++) { ss += redS[t * 64 + j]; qq += redQ[t * 64 + j]; }
        float m = ss * (1.f / HDIM);
        float v = qq * (1.f / HDIM) - m * m;
        mrow[t] = m;
        rrow[t] = rsqrtf(v + 1e-5f);
    }
    __syncthreads();
#pragma unroll
    for (int i = 0; i < 8; i++) {
        int r = ry * 8 + i;
        float m = mrow[r], rs = rrow[r];
        float* dst = out + (size_t)(row0 + r) * HDIM;
#pragma unroll
        for (int j = 0; j < 8; j++) {
            int c = cx + 64 * j;
            dst[c] = (acc[i][j] - m) * rs * lns[c] + lnb[c];
        }
    }
}

// ---------------- route stage 1: r0 = relu(obs_n @ Wr0[role] + br0) -------
// grouped gathered GEMM: 64-row tile, N=128, K=256
__global__ __launch_bounds__(256) void k_route1(
    const float* __restrict__ Wr0, const float* __restrict__ br0)
{
    const int role = blockIdx.y;
    const int cnt = g_cnt[role];
    const int t0 = blockIdx.x * 64;
    if (t0 >= cnt) return;
    __shared__ __align__(16) float As[16][72];
    __shared__ __align__(16) float Bs[16][128];
    __shared__ int rowidx[64];
    const int t = threadIdx.x;
    if (t < 64) {
        int p = t0 + t;
        rowidx[t] = g_rows[role * NROWS + (p < cnt ? p : t0)];
    }
    __syncthreads();
    const int cx = t & 15, ry = t >> 4;
    float acc[4][8];
#pragma unroll
    for (int i = 0; i < 4; i++)
#pragma unroll
        for (int j = 0; j < 8; j++) acc[i][j] = 0.f;
    const int ar = t >> 2, ak = (t & 3) << 2;
    for (int k0 = 0; k0 < DOBS; k0 += 16) {
        float4 v = *reinterpret_cast<const float4*>(g_obsn + (size_t)rowidx[ar] * DOBS + k0 + ak);
        As[ak][ar] = v.x; As[ak + 1][ar] = v.y; As[ak + 2][ar] = v.z; As[ak + 3][ar] = v.w;
#pragma unroll
        for (int i = 0; i < 2; i++) {
            int idx = t + i * 256;
            int kk = idx >> 5, nn = (idx & 31) << 2;
            float4 w = *reinterpret_cast<const float4*>(Wr0 + ((size_t)role * DOBS + k0 + kk) * 128 + nn);
            *reinterpret_cast<float4*>(&Bs[kk][nn]) = w;
        }
        __syncthreads();
#pragma unroll
        for (int kk = 0; kk < 16; kk++) {
            float4 a4 = *reinterpret_cast<const float4*>(&As[kk][ry * 4]);
            float a[4] = {a4.x, a4.y, a4.z, a4.w};
            float b[8];
#pragma unroll
            for (int j = 0; j < 8; j++) b[j] = Bs[kk][cx + 16 * j];
#pragma unroll
            for (int i = 0; i < 4; i++)
#pragma unroll
                for (int j = 0; j < 8; j++) acc[i][j] = fmaf(a[i], b[j], acc[i][j]);
        }
        __syncthreads();
    }
    float bv[8];
#pragma unroll
    for (int j = 0; j < 8; j++) bv[j] = br0[role * 128 + cx + 16 * j];
#pragma unroll
    for (int i = 0; i < 4; i++) {
        int r = ry * 4 + i;
        if (t0 + r < cnt) {
            float* dst = g_r0 + (size_t)rowidx[r] * 128;
#pragma unroll
            for (int j = 0; j < 8; j++)
                dst[cx + 16 * j] = fmaxf(acc[i][j] + bv[j], 0.f);
        }
    }
}

// ---------------- route stage 2: e1 += relu(r0 @ Wr1[role] + br1) ---------
// 32-row tile, N=512, K=128
__global__ __launch_bounds__(256) void k_route2(
    const float* __restrict__ Wr1, const float* __restrict__ br1)
{
    const int role = blockIdx.y;
    const int cnt = g_cnt[role];
    const int t0 = blockIdx.x * 32;
    if (t0 >= cnt) return;
    __shared__ __align__(16) float As[16][40];
    __shared__ __align__(16) float Bs[16][512];
    __shared__ int rowidx[32];
    const int t = threadIdx.x;
    if (t < 32) {
        int p = t0 + t;
        rowidx[t] = g_rows[role * NROWS + (p < cnt ? p : t0)];
    }
    __syncthreads();
    const int cx = t & 63, ry = t >> 6;
    float acc[8][8];
#pragma unroll
    for (int i = 0; i < 8; i++)
#pragma unroll
        for (int j = 0; j < 8; j++) acc[i][j] = 0.f;
    const int ar = t >> 3, ak = (t & 7) << 1;
    for (int k0 = 0; k0 < 128; k0 += 16) {
        float2 v = *reinterpret_cast<const float2*>(g_r0 + (size_t)rowidx[ar] * 128 + k0 + ak);
        As[ak][ar] = v.x; As[ak + 1][ar] = v.y;
#pragma unroll
        for (int i = 0; i < 8; i++) {
            int idx = t + i * 256;
            int kk = idx >> 7, nn = (idx & 127) << 2;
            float4 w = *reinterpret_cast<const float4*>(Wr1 + ((size_t)role * 128 + k0 + kk) * HDIM + nn);
            *reinterpret_cast<float4*>(&Bs[kk][nn]) = w;
        }
        __syncthreads();
#pragma unroll
        for (int kk = 0; kk < 16; kk++) {
            float4 a0 = *reinterpret_cast<const float4*>(&As[kk][ry * 8]);
            float4 a1 = *reinterpret_cast<const float4*>(&As[kk][ry * 8 + 4]);
            float a[8] = {a0.x, a0.y, a0.z, a0.w, a1.x, a1.y, a1.z, a1.w};
            float b[8];
#pragma unroll
            for (int j = 0; j < 8; j++) b[j] = Bs[kk][cx + 64 * j];
#pragma unroll
            for (int i = 0; i < 8; i++)
#pragma unroll
                for (int j = 0; j < 8; j++) acc[i][j] = fmaf(a[i], b[j], acc[i][j]);
        }
        __syncthreads();
    }
    float bv[8];
#pragma unroll
    for (int j = 0; j < 8; j++) bv[j] = br1[role * HDIM + cx + 64 * j];
#pragma unroll
    for (int i = 0; i < 8; i++) {
        int r = ry * 8 + i;
        if (t0 + r < cnt) {
            float* dst = g_e1 + (size_t)rowidx[r] * HDIM;
#pragma unroll
            for (int j = 0; j < 8; j++) {
                int c = cx + 64 * j;
                dst[c] += fmaxf(acc[i][j] + bv[j], 0.f);
            }
        }
    }
}

// ---------------- heads: 512->64->32->A per role, fused, masked -----------
// 64-row tile per block; all head weights staged in dynamic smem.
__global__ __launch_bounds__(256) void k_heads(
    const float* __restrict__ Wh0, const float* __restrict__ bh0,
    const float* __restrict__ Wh1, const float* __restrict__ bh1,
    const float* __restrict__ Wh2, const float* __restrict__ bh2,
    const float* __restrict__ avail, float* __restrict__ outlog)
{
    const int role = blockIdx.y;
    const int cnt = g_cnt[role];
    const int t0 = blockIdx.x * 64;
    if (t0 >= cnt) return;
    extern __shared__ __align__(16) float sm[];
    float* Wh0s = sm;              // 32768
    float* Wh1s = sm + 32768;      // 2048
    float* Wh2s = sm + 34816;      // 1024
    float* bh0s = sm + 35840;      // 64
    float* bh1s = sm + 35904;      // 32
    float* bh2s = sm + 35936;      // 32
    float* h0s  = sm + 35968;      // 64*65
    float* h1s  = sm + 40128;      // 64*33
    float* As   = sm + 42240;      // 16*72
    int* rowidx = (int*)(sm + 43392); // 64
    const int t = threadIdx.x;
    {
        const float4* src = (const float4*)(Wh0 + (size_t)role * HDIM * 64);
        float4* dst = (float4*)Wh0s;
#pragma unroll
        for (int i = 0; i < 32; i++) dst[t + i * 256] = src[t + i * 256];
        const float4* s1 = (const float4*)(Wh1 + (size_t)role * 64 * 32);
#pragma unroll
        for (int i = 0; i < 2; i++) ((float4*)Wh1s)[t + i * 256] = s1[t + i * 256];
        ((float4*)Wh2s)[t] = ((const float4*)(Wh2 + (size_t)role * 32 * 32))[t];
        if (t < 64) bh0s[t] = bh0[role * 64 + t];
        if (t < 32) { bh1s[t] = bh1[role * 32 + t]; bh2s[t] = bh2[role * 32 + t]; }
        if (t < 64) {
            int p = t0 + t;
            rowidx[t] = g_rows[role * NROWS + (p < cnt ? p : t0)];
        }
    }
    __syncthreads();

    // h0 = relu(e1 @ Wh0 + bh0) : 64x64, K=512
    const int cx = t & 15, ry = t >> 4;
    float acc0[4][4];
#pragma unroll
    for (int i = 0; i < 4; i++)
#pragma unroll
        for (int j = 0; j < 4; j++) acc0[i][j] = 0.f;
    const int ar = t >> 2, ak = (t & 3) << 2;
    for (int k0 = 0; k0 < HDIM; k0 += 16) {
        float4 v = *reinterpret_cast<const float4*>(g_e1 + (size_t)rowidx[ar] * HDIM + k0 + ak);
        As[ak * 72 + ar] = v.x; As[(ak + 1) * 72 + ar] = v.y;
        As[(ak + 2) * 72 + ar] = v.z; As[(ak + 3) * 72 + ar] = v.w;
        __syncthreads();
#pragma unroll
        for (int kk = 0; kk < 16; kk++) {
            float4 a4 = *reinterpret_cast<const float4*>(&As[kk * 72 + ry * 4]);
            float a[4] = {a4.x, a4.y, a4.z, a4.w};
            float b[4];
#pragma unroll
            for (int j = 0; j < 4; j++) b[j] = Wh0s[(k0 + kk) * 64 + cx + 16 * j];
#pragma unroll
            for (int i = 0; i < 4; i++)
#pragma unroll
                for (int j = 0; j < 4; j++) acc0[i][j] = fmaf(a[i], b[j], acc0[i][j]);
        }
        __syncthreads();
    }
#pragma unroll
    for (int i = 0; i < 4; i++) {
        int r = ry * 4 + i;
#pragma unroll
        for (int j = 0; j < 4; j++) {
            int c = cx + 16 * j;
            h0s[r * 65 + c] = fmaxf(acc0[i][j] + bh0s[c], 0.f);
        }
    }
    __syncthreads();

    // h1 = relu(h0 @ Wh1 + bh1) : 64x32, K=64
    const int c2 = t & 7, r2 = t >> 3;
    float acc1[2][4];
#pragma unroll
    for (int i = 0; i < 2; i++)
#pragma unroll
        for (int j = 0; j < 4; j++) acc1[i][j] = 0.f;
#pragma unroll
    for (int k = 0; k < 64; k++) {
        float a0 = h0s[(2 * r2) * 65 + k];
        float a1 = h0s[(2 * r2 + 1) * 65 + k];
#pragma unroll
        for (int j = 0; j < 4; j++) {
            float b = Wh1s[k * 32 + c2 + 8 * j];
            acc1[0][j] = fmaf(a0, b, acc1[0][j]);
            acc1[1][j] = fmaf(a1, b, acc1[1][j]);
        }
    }
#pragma unroll
    for (int i = 0; i < 2; i++)
#pragma unroll
        for (int j = 0; j < 4; j++) {
            int c = c2 + 8 * j;
            h1s[(2 * r2 + i) * 33 + c] = fmaxf(acc1[i][j] + bh1s[c], 0.f);
        }
    __syncthreads();

    // logits = h1 @ Wh2 + bh2, then mask + scatter
    float acc2[2][4];
#pragma unroll
    for (int i = 0; i < 2; i++)
#pragma unroll
        for (int j = 0; j < 4; j++) acc2[i][j] = 0.f;
#pragma unroll
    for (int k = 0; k < 32; k++) {
        float a0 = h1s[(2 * r2) * 33 + k];
        float a1 = h1s[(2 * r2 + 1) * 33 + k];
#pragma unroll
        for (int j = 0; j < 4; j++) {
            float b = Wh2s[k * 32 + c2 + 8 * j];
            acc2[0][j] = fmaf(a0, b, acc2[0][j]);
            acc2[1][j] = fmaf(a1, b, acc2[1][j]);
        }
    }
#pragma unroll
    for (int i = 0; i < 2; i++) {
        int rr = 2 * r2 + i;
        if (t0 + rr < cnt) {
            int g = rowidx[rr];
#pragma unroll
            for (int j = 0; j < 4; j++) {
                int c = c2 + 8 * j;
                float v = acc2[i][j] + bh2s[c];
                float av = avail[(size_t)g * NA + c];
                outlog[(size_t)g * NA + c] = (av > 0.5f) ? v : -1e10f;
            }
        }
    }
}

// ---------------- launch ---------------------------------------------------
extern "C" void kernel_launch(void* const* d_in, const int* in_sizes, int n_in,
                              void* d_out, int out_size) {
    const float* rnn   = (const float*)d_in[0];
    const float* obs   = (const float*)d_in[1];
    const float* avail = (const float*)d_in[3];
    const int*   roles = (const int*)  d_in[4];
    const float* fns   = (const float*)d_in[5];
    const float* fnb   = (const float*)d_in[6];
    const float* W0    = (const float*)d_in[7];
    const float* b0    = (const float*)d_in[8];
    const float* l0s   = (const float*)d_in[9];
    const float* l0b   = (const float*)d_in[10];
    const float* W1    = (const float*)d_in[11];
    const float* b1    = (const float*)d_in[12];
    const float* l1s   = (const float*)d_in[13];
    const float* l1b   = (const float*)d_in[14];
    const float* Wr0   = (const float*)d_in[15];
    const float* br0   = (const float*)d_in[16];
    const float* Wr1   = (const float*)d_in[17];
    const float* br1   = (const float*)d_in[18];
    const float* Wh0   = (const float*)d_in[19];
    const float* bh0   = (const float*)d_in[20];
    const float* Wh1   = (const float*)d_in[21];
    const float* bh1   = (const float*)d_in[22];
    const float* Wh2   = (const float*)d_in[23];
    const float* bh2   = (const float*)d_in[24];
    float* out = (float*)d_out;

    void *p_obsn, *p_e0, *p_e1;
    cudaGetSymbolAddress(&p_obsn, g_obsn);
    cudaGetSymbolAddress(&p_e0, g_e0);
    cudaGetSymbolAddress(&p_e1, g_e1);

    int logit_off = out_size - NROWS * NA;
    if (logit_off < 0) logit_off = 0;
    float* outlog = out + logit_off;

    cudaFuncSetAttribute(k_heads, cudaFuncAttributeMaxDynamicSharedMemorySize, 43456 * 4);

    if (logit_off > 0)
        k_copy4<<<(logit_off / 4 + 255) / 256, 256>>>((const float4*)rnn, (float4*)out, logit_off / 4);

    k_zero_cnt<<<1, 32>>>();
    k_bucket<<<NROWS / 256, 256>>>(roles);
    k_ln_obs<<<NROWS / 8, 256>>>(obs, fns, fnb);
    k_gemm_ln<<<NROWS / 32, 256>>>((const float*)p_obsn, W0, b0, l0s, l0b, (float*)p_e0, DOBS);
    k_gemm_ln<<<NROWS / 32, 256>>>((const float*)p_e0, W1, b1, l1s, l1b, (float*)p_e1, HDIM);
    k_route1<<<dim3(NROWS / 64, NROLES), 256>>>(Wr0, br0);
    k_route2<<<dim3(NROWS / 32, NROLES), 256>>>(Wr1, br1);
    k_heads<<<dim3(NROWS / 64, NROLES), 256, 43456 * 4>>>(Wh0, bh0, Wh1, bh1, Wh2, bh2, avail, outlog);
}